// round 13
// baseline (speedup 1.0000x reference)
#include <cuda_runtime.h>
#include <cuda_fp16.h>
#include <cstdint>

#define NEMB 1024
#define HS 64
#define BB 8
#define TT 2048
#define BT (BB*TT)
#define LDB 72          // 16-bit elem row stride for 64-wide tiles (144B)
#define LDX 40          // fp16 row stride for 32-wide X tiles
#define NQT (TT/64)
#define CHK 8
#define MAXC 4
#define LOG2E 1.4426950408889634f

// fp16 storage: Q single, K single (pre-scaled by log2e), V single
__device__ __align__(16) __half gQ[BT*HS];
__device__ __align__(16) __half gK[BT*HS];
__device__ __align__(16) __half gV[BT*HS];
// fp16 weights, [mat][k][n]
__device__ __align__(16) __half gW3[3*NEMB*HS];
// split-K partials: O as fp16, m/l fp32
__device__ __align__(16) __half gOp[BB*NQT*MAXC*64*HS];
__device__ float gM[BB*NQT*MAXC*64];
__device__ float gL[BB*NQT*MAXC*64];

__device__ __forceinline__ unsigned su32(const void* p) {
    return (unsigned)__cvta_generic_to_shared(p);
}
__device__ __forceinline__ void cpa16(unsigned dst, const void* src) {
    asm volatile("cp.async.cg.shared.global [%0], [%1], 16;\n" :: "r"(dst), "l"(src));
}
__device__ __forceinline__ void cpcommit() { asm volatile("cp.async.commit_group;\n"); }
template<int N> __device__ __forceinline__ void cpwait() {
    asm volatile("cp.async.wait_group %0;\n" :: "n"(N));
}
__device__ __forceinline__ void ldsm4(unsigned a, unsigned* r) {
    asm volatile("ldmatrix.sync.aligned.m8n8.x4.shared.b16 {%0,%1,%2,%3},[%4];\n"
                 : "=r"(r[0]), "=r"(r[1]), "=r"(r[2]), "=r"(r[3]) : "r"(a));
}
__device__ __forceinline__ void ldsm4t(unsigned a, unsigned* r) {
    asm volatile("ldmatrix.sync.aligned.m8n8.x4.trans.shared.b16 {%0,%1,%2,%3},[%4];\n"
                 : "=r"(r[0]), "=r"(r[1]), "=r"(r[2]), "=r"(r[3]) : "r"(a));
}
__device__ __forceinline__ void mmah(float* c, const unsigned* a, unsigned b0, unsigned b1) {
    asm volatile("mma.sync.aligned.m16n8k16.row.col.f32.f16.f16.f32 "
                 "{%0,%1,%2,%3},{%4,%5,%6,%7},{%8,%9},{%0,%1,%2,%3};\n"
                 : "+f"(c[0]), "+f"(c[1]), "+f"(c[2]), "+f"(c[3])
                 : "r"(a[0]), "r"(a[1]), "r"(a[2]), "r"(a[3]), "r"(b0), "r"(b1));
}
__device__ __forceinline__ unsigned packh2(float x, float y) {
    __half2 hh = __floats2half2_rn(x, y);
    return *(unsigned*)&hh;
}
// hardware exp2 / rcp (one MUFU each, independent of fast-math flags)
__device__ __forceinline__ float ex2(float x) {
    float r;
    asm("ex2.approx.ftz.f32 %0, %1;" : "=f"(r) : "f"(x));
    return r;
}
__device__ __forceinline__ float rcp(float x) {
    float r;
    asm("rcp.approx.ftz.f32 %0, %1;" : "=f"(r) : "f"(x));
    return r;
}

// ---------------------------------------------------------------------------
// Convert weights to fp16 (once).
// ---------------------------------------------------------------------------
__global__ void splitw_kernel(const float* __restrict__ Wq,
                              const float* __restrict__ Wk,
                              const float* __restrict__ Wv)
{
    const float* Wsrc[3] = {Wq, Wk, Wv};
    int off = (blockIdx.x * 256 + threadIdx.x) * 4;
    #pragma unroll
    for (int mat = 0; mat < 3; ++mat) {
        float4 v = *(const float4*)&Wsrc[mat][off];
        uint2 p = make_uint2(packh2(v.x, v.y), packh2(v.z, v.w));
        *(uint2*)&gW3[mat*NEMB*HS + off] = p;
    }
}

// ---------------------------------------------------------------------------
// Projection: 128 rows of X per CTA -> Q,K,V. Single-term fp16: X·W.
// ---------------------------------------------------------------------------
#define PJ_BLK 24064
#define PJ_X(s)      ((s)*PJ_BLK)
#define PJ_W(s,mat)  ((s)*PJ_BLK + 10240 + (mat)*4608)
static const int PROJ_SMEM = 2*PJ_BLK;   // 48128

__global__ __launch_bounds__(512) void proj_kernel(const float* __restrict__ x)
{
    extern __shared__ char smc[];
    const unsigned sb = su32(smc);
    const int tid = threadIdx.x, lane = tid & 31, wid = tid >> 5;
    const int wm = wid & 7, wn = wid >> 3;
    const int bt0 = blockIdx.x * 128;

    const int xrow0 = tid >> 3, xc0 = (tid & 7) * 4;
    const int xrow1 = (tid + 512) >> 3, xc1 = ((tid + 512) & 7) * 4;

    float acc[3][4][4];
    #pragma unroll
    for (int m = 0; m < 3; ++m)
        #pragma unroll
        for (int t = 0; t < 4; ++t)
            #pragma unroll
            for (int r = 0; r < 4; ++r) acc[m][t][r] = 0.f;

    #pragma unroll
    for (int r = 0; r < 2; ++r) {
        int u = tid + 512*r;
        if (u < 768) {
            int mat = u >> 8, rem = u & 255;
            int row = rem >> 3, c16 = rem & 7;
            const char* src = (const char*)(gW3 + (size_t)mat*NEMB*HS)
                            + ((size_t)row*HS + c16*8) * 2;
            cpa16(sb + PJ_W(0, mat) + row*144 + c16*16, src);
        }
    }
    cpcommit();
    float4 xr0, xr1;
    xr0 = *(const float4*)&x[(size_t)(bt0+xrow0)*NEMB + xc0];
    xr1 = *(const float4*)&x[(size_t)(bt0+xrow1)*NEMB + xc1];
    *(uint2*)((__half*)(smc + PJ_X(0)) + xrow0*LDX + xc0) =
        make_uint2(packh2(xr0.x, xr0.y), packh2(xr0.z, xr0.w));
    *(uint2*)((__half*)(smc + PJ_X(0)) + xrow1*LDX + xc1) =
        make_uint2(packh2(xr1.x, xr1.y), packh2(xr1.z, xr1.w));
    xr0 = *(const float4*)&x[(size_t)(bt0+xrow0)*NEMB + 32 + xc0];
    xr1 = *(const float4*)&x[(size_t)(bt0+xrow1)*NEMB + 32 + xc1];

    int buf = 0;
    for (int kt = 0; kt < 32; ++kt) {
        cpwait<0>();
        __syncthreads();
        if (kt < 31) {
            #pragma unroll
            for (int r = 0; r < 2; ++r) {
                int u = tid + 512*r;
                if (u < 768) {
                    int mat = u >> 8, rem = u & 255;
                    int row = rem >> 3, c16 = rem & 7;
                    const char* src = (const char*)(gW3 + (size_t)mat*NEMB*HS)
                                    + ((size_t)((kt+1)*32 + row)*HS + c16*8) * 2;
                    cpa16(sb + PJ_W(buf^1, mat) + row*144 + c16*16, src);
                }
            }
            cpcommit();
            *(uint2*)((__half*)(smc + PJ_X(buf^1)) + xrow0*LDX + xc0) =
                make_uint2(packh2(xr0.x, xr0.y), packh2(xr0.z, xr0.w));
            *(uint2*)((__half*)(smc + PJ_X(buf^1)) + xrow1*LDX + xc1) =
                make_uint2(packh2(xr1.x, xr1.y), packh2(xr1.z, xr1.w));
            if (kt < 30) {
                xr0 = *(const float4*)&x[(size_t)(bt0+xrow0)*NEMB + (kt+2)*32 + xc0];
                xr1 = *(const float4*)&x[(size_t)(bt0+xrow1)*NEMB + (kt+2)*32 + xc1];
            }
        }

        #pragma unroll
        for (int kk = 0; kk < 2; ++kk) {
            unsigned ah[4];
            unsigned ao = (unsigned)(((wm*16 + (lane&15))*LDX + kk*16 + (lane>>4)*8) * 2);
            ldsm4(sb + PJ_X(buf) + ao, ah);
            #pragma unroll
            for (int mat = 0; mat < 3; ++mat) {
                #pragma unroll
                for (int nb = 0; nb < 2; ++nb) {
                    unsigned bh[4];
                    unsigned bo = (unsigned)(((kk*16 + (lane&15))*LDB +
                                              wn*32 + nb*16 + (lane>>4)*8) * 2);
                    ldsm4t(sb + PJ_W(buf, mat) + bo, bh);
                    mmah(acc[mat][nb*2],   ah, bh[0], bh[1]);
                    mmah(acc[mat][nb*2+1], ah, bh[2], bh[3]);
                }
            }
        }
        buf ^= 1;
    }

    const int r0 = bt0 + wm*16 + (lane >> 2);
    #pragma unroll
    for (int nt = 0; nt < 4; ++nt) {
        int col = wn*32 + nt*8 + 2*(lane & 3);
        *(unsigned*)&gQ[(size_t)r0*HS + col]     = packh2(acc[0][nt][0], acc[0][nt][1]);
        *(unsigned*)&gQ[(size_t)(r0+8)*HS + col] = packh2(acc[0][nt][2], acc[0][nt][3]);
        *(unsigned*)&gK[(size_t)r0*HS + col] =
            packh2(acc[1][nt][0]*LOG2E, acc[1][nt][1]*LOG2E);
        *(unsigned*)&gK[(size_t)(r0+8)*HS + col] =
            packh2(acc[1][nt][2]*LOG2E, acc[1][nt][3]*LOG2E);
        *(unsigned*)&gV[(size_t)r0*HS + col]     = packh2(acc[2][nt][0], acc[2][nt][1]);
        *(unsigned*)&gV[(size_t)(r0+8)*HS + col] = packh2(acc[2][nt][2], acc[2][nt][3]);
    }
}

// ---------------------------------------------------------------------------
// Flash attention, split-K, fp16 single-term S and PV. Base-2 softmax with
// hardware ex2.approx.
// ---------------------------------------------------------------------------
#define AT_K(s) ((s)*18432)
#define AT_V(s) ((s)*18432 + 9216)
#define AT_Q 36864
static const int ATTN_SMEM = 46080;

__global__ __launch_bounds__(128, 4) void attn_kernel(float* __restrict__ out)
{
    const int c  = blockIdx.x;
    const int qt = NQT - 1 - blockIdx.y;
    const int b  = blockIdx.z;
    const int nch = (qt >> 3) + 1;
    if (c >= nch) return;
    const int kt0 = c * CHK;
    const int kt1 = min(qt, kt0 + CHK - 1);
    const int t0 = qt * 64;

    extern __shared__ char smc[];
    const unsigned sb = su32(smc);
    const int tid = threadIdx.x, lane = tid & 31, w = tid >> 5;
    const int lr = lane >> 2;
    const int lc2 = 2 * (lane & 3);

    unsigned d16[4];
    #pragma unroll
    for (int r = 0; r < 4; ++r) {
        int u = tid + 128*r;
        d16[r] = (unsigned)((u>>3)*144 + (u&7)*16);
    }

    {
        const char* gq = (const char*)gQ + (size_t)(b*TT + t0)*128;
        #pragma unroll
        for (int r = 0; r < 4; ++r) {
            int u = tid + 128*r;
            cpa16(sb + AT_Q + d16[r], gq + (size_t)u*16);
        }
        cpcommit();
    }
    {
        size_t gb = (size_t)(b*TT + kt0*64)*128;
        #pragma unroll
        for (int r = 0; r < 4; ++r) {
            int u = tid + 128*r;
            size_t go = gb + (size_t)u*16;
            cpa16(sb + AT_K(0) + d16[r], (const char*)gK + go);
            cpa16(sb + AT_V(0) + d16[r], (const char*)gV + go);
        }
        cpcommit();
    }

    cpwait<1>();
    __syncthreads();
    unsigned qh[4][4];
    #pragma unroll
    for (int kk = 0; kk < 4; ++kk) {
        unsigned ao = (unsigned)(((w*16 + (lane&15))*LDB + kk*16 + (lane>>4)*8) * 2);
        ldsm4(sb + AT_Q + ao, qh[kk]);
    }

    float o[8][4];
    #pragma unroll
    for (int t = 0; t < 8; ++t)
        #pragma unroll
        for (int r = 0; r < 4; ++r) o[t][r] = 0.f;
    float m0 = -1e30f, m1 = -1e30f, l0 = 0.f, l1 = 0.f;

    int buf = 0;
    for (int kt = kt0; kt <= kt1; ++kt) {
        cpwait<0>();
        __syncthreads();
        if (kt < kt1) {
            size_t gb = (size_t)(b*TT + (kt+1)*64)*128;
            #pragma unroll
            for (int r = 0; r < 4; ++r) {
                int u = tid + 128*r;
                size_t go = gb + (size_t)u*16;
                cpa16(sb + AT_K(buf^1) + d16[r], (const char*)gK + go);
                cpa16(sb + AT_V(buf^1) + d16[r], (const char*)gV + go);
            }
            cpcommit();
        }

        float st[8][4];
        #pragma unroll
        for (int t = 0; t < 8; ++t)
            #pragma unroll
            for (int r = 0; r < 4; ++r) st[t][r] = 0.f;
        #pragma unroll
        for (int kk = 0; kk < 4; ++kk) {
            #pragma unroll
            for (int kb = 0; kb < 4; ++kb) {
                unsigned kh[4];
                unsigned ko = (unsigned)(((kb*16 + (lane&15))*LDB + kk*16 + (lane>>4)*8) * 2);
                ldsm4(sb + AT_K(buf) + ko, kh);
                mmah(st[kb*2],   qh[kk], kh[0], kh[2]);
                mmah(st[kb*2+1], qh[kk], kh[1], kh[3]);
            }
        }

        if (kt == qt) {
            int r0 = w*16 + lr, r1 = r0 + 8;
            #pragma unroll
            for (int nt = 0; nt < 8; ++nt) {
                int cc = nt*8 + lc2;
                if (cc     > r0) st[nt][0] = -1e30f;
                if (cc + 1 > r0) st[nt][1] = -1e30f;
                if (cc     > r1) st[nt][2] = -1e30f;
                if (cc + 1 > r1) st[nt][3] = -1e30f;
            }
        }

        float mx0 = -1e30f, mx1 = -1e30f;
        #pragma unroll
        for (int nt = 0; nt < 8; ++nt) {
            mx0 = fmaxf(mx0, fmaxf(st[nt][0], st[nt][1]));
            mx1 = fmaxf(mx1, fmaxf(st[nt][2], st[nt][3]));
        }
        mx0 = fmaxf(mx0, __shfl_xor_sync(0xffffffffu, mx0, 1));
        mx0 = fmaxf(mx0, __shfl_xor_sync(0xffffffffu, mx0, 2));
        mx1 = fmaxf(mx1, __shfl_xor_sync(0xffffffffu, mx1, 1));
        mx1 = fmaxf(mx1, __shfl_xor_sync(0xffffffffu, mx1, 2));
        float mn0 = fmaxf(m0, mx0), mn1 = fmaxf(m1, mx1);
        float a0 = ex2(m0 - mn0), a1 = ex2(m1 - mn1);
        float s0 = 0.f, s1 = 0.f;
        #pragma unroll
        for (int nt = 0; nt < 8; ++nt) {
            st[nt][0] = ex2(st[nt][0] - mn0);
            st[nt][1] = ex2(st[nt][1] - mn0);
            st[nt][2] = ex2(st[nt][2] - mn1);
            st[nt][3] = ex2(st[nt][3] - mn1);
            s0 += st[nt][0] + st[nt][1];
            s1 += st[nt][2] + st[nt][3];
        }
        l0 = l0 * a0 + s0; l1 = l1 * a1 + s1;
        m0 = mn0; m1 = mn1;
        #pragma unroll
        for (int nt = 0; nt < 8; ++nt) {
            o[nt][0] *= a0; o[nt][1] *= a0; o[nt][2] *= a1; o[nt][3] *= a1;
        }

        unsigned p[4][4];
        #pragma unroll
        for (int t = 0; t < 4; ++t) {
            p[t][0] = packh2(st[2*t][0],   st[2*t][1]);
            p[t][1] = packh2(st[2*t][2],   st[2*t][3]);
            p[t][2] = packh2(st[2*t+1][0], st[2*t+1][1]);
            p[t][3] = packh2(st[2*t+1][2], st[2*t+1][3]);
        }
        #pragma unroll
        for (int t = 0; t < 4; ++t) {
            #pragma unroll
            for (int nb = 0; nb < 4; ++nb) {
                unsigned vh[4];
                unsigned vo = (unsigned)(((t*16 + (lane&15))*LDB + nb*16 + (lane>>4)*8) * 2);
                ldsm4t(sb + AT_V(buf) + vo, vh);
                mmah(o[nb*2],   p[t], vh[0], vh[1]);
                mmah(o[nb*2+1], p[t], vh[2], vh[3]);
            }
        }
        buf ^= 1;
    }

    l0 += __shfl_xor_sync(0xffffffffu, l0, 1);
    l0 += __shfl_xor_sync(0xffffffffu, l0, 2);
    l1 += __shfl_xor_sync(0xffffffffu, l1, 1);
    l1 += __shfl_xor_sync(0xffffffffu, l1, 2);

    const int rloc = w*16 + lr;
    if (nch == 1) {
        float i0 = rcp(l0), i1 = rcp(l1);
        size_t gr0 = (size_t)(b*TT + t0 + rloc);
        #pragma unroll
        for (int nt = 0; nt < 8; ++nt) {
            int col = nt*8 + lc2;
            *(float2*)&out[gr0*HS + col]     = make_float2(o[nt][0]*i0, o[nt][1]*i0);
            *(float2*)&out[(gr0+8)*HS + col] = make_float2(o[nt][2]*i1, o[nt][3]*i1);
        }
    } else {
        size_t slot = (size_t)(b*NQT + qt)*MAXC + c;
        __half* Op = gOp + slot*(64*HS);
        #pragma unroll
        for (int nt = 0; nt < 8; ++nt) {
            int col = nt*8 + lc2;
            *(unsigned*)&Op[rloc*HS + col]     = packh2(o[nt][0], o[nt][1]);
            *(unsigned*)&Op[(rloc+8)*HS + col] = packh2(o[nt][2], o[nt][3]);
        }
        if ((lane & 3) == 0) {
            gM[slot*64 + rloc] = m0;     gL[slot*64 + rloc] = l0;
            gM[slot*64 + rloc + 8] = m1; gL[slot*64 + rloc + 8] = l1;
        }
    }
}

// ---------------------------------------------------------------------------
// Merge split-K partials (fp16 partials, base-2 maxes, hardware ex2/rcp).
// ---------------------------------------------------------------------------
__global__ __launch_bounds__(256) void merge_kernel(float* __restrict__ out)
{
    const int qt = CHK + blockIdx.x;
    const int b  = blockIdx.y;
    const int z  = blockIdx.z;
    const int nch = (qt >> 3) + 1;
    const int tid = threadIdx.x;
    const int row = tid >> 2;
    const int col = z*16 + (tid & 3) * 4;
    const size_t slot0 = (size_t)(b*NQT + qt)*MAXC;

    float ms = -1e30f;
    float mv[MAXC];
    #pragma unroll
    for (int c = 0; c < MAXC; ++c)
        if (c < nch) { mv[c] = gM[(slot0 + c)*64 + row]; ms = fmaxf(ms, mv[c]); }
    float lsum = 0.f;
    float sc[MAXC];
    #pragma unroll
    for (int c = 0; c < MAXC; ++c)
        if (c < nch) {
            sc[c] = ex2(mv[c] - ms);
            lsum += gL[(slot0 + c)*64 + row] * sc[c];
        }
    float inv = rcp(lsum);

    float4 acc = make_float4(0.f, 0.f, 0.f, 0.f);
    #pragma unroll
    for (int c = 0; c < MAXC; ++c)
        if (c < nch) {
            uint2 pv = *(const uint2*)&gOp[(slot0 + c)*(64*HS) + row*HS + col];
            float2 v0 = __half22float2(*(__half2*)&pv.x);
            float2 v1 = __half22float2(*(__half2*)&pv.y);
            acc.x += v0.x * sc[c]; acc.y += v0.y * sc[c];
            acc.z += v1.x * sc[c]; acc.w += v1.y * sc[c];
        }
    acc.x *= inv; acc.y *= inv; acc.z *= inv; acc.w *= inv;
    *(float4*)&out[(size_t)(b*TT + qt*64 + row)*HS + col] = acc;
}

// ---------------------------------------------------------------------------
extern "C" void kernel_launch(void* const* d_in, const int* in_sizes, int n_in,
                              void* d_out, int out_size)
{
    const float* x  = (const float*)d_in[0];
    const float* Wq = (const float*)d_in[1];
    const float* Wk = (const float*)d_in[2];
    const float* Wv = (const float*)d_in[3];
    float* out = (float*)d_out;
    (void)in_sizes; (void)n_in; (void)out_size;

    cudaFuncSetAttribute(proj_kernel, cudaFuncAttributeMaxDynamicSharedMemorySize, PROJ_SMEM);
    cudaFuncSetAttribute(attn_kernel, cudaFuncAttributeMaxDynamicSharedMemorySize, ATTN_SMEM);

    splitw_kernel<<<NEMB*HS/1024, 256>>>(Wq, Wk, Wv);
    proj_kernel<<<BT/128, 512, PROJ_SMEM>>>(x);
    attn_kernel<<<dim3(MAXC, NQT, BB), 128, ATTN_SMEM>>>(out);
    merge_kernel<<<dim3(NQT - CHK, BB, 4), 256>>>(out);
}

// round 14
// speedup vs baseline: 1.4739x; 1.4739x over previous
#include <cuda_runtime.h>
#include <cuda_fp16.h>
#include <cstdint>

#define NEMB 1024
#define HS 64
#define BB 8
#define TT 2048
#define BT (BB*TT)
#define LDB 72          // 16-bit elem row stride for 64-wide tiles (144B)
#define LDX 40          // fp16 row stride for 32-wide X tiles
#define NQT (TT/64)
#define CHK 8
#define MAXC 4
#define LOG2E 1.4426950408889634f
#define ONE_H2 0x3C003C00u   // half2(1.0, 1.0)

// fp16 storage: Q single, K single (pre-scaled by log2e), V single
__device__ __align__(16) __half gQ[BT*HS];
__device__ __align__(16) __half gK[BT*HS];
__device__ __align__(16) __half gV[BT*HS];
// fp16 weights, [mat][k][n]
__device__ __align__(16) __half gW3[3*NEMB*HS];
// split-K partials: O as fp16, m/l fp32
__device__ __align__(16) __half gOp[BB*NQT*MAXC*64*HS];
__device__ float gM[BB*NQT*MAXC*64];
__device__ float gL[BB*NQT*MAXC*64];

__device__ __forceinline__ unsigned su32(const void* p) {
    return (unsigned)__cvta_generic_to_shared(p);
}
__device__ __forceinline__ void cpa16(unsigned dst, const void* src) {
    asm volatile("cp.async.cg.shared.global [%0], [%1], 16;\n" :: "r"(dst), "l"(src));
}
__device__ __forceinline__ void cpcommit() { asm volatile("cp.async.commit_group;\n"); }
template<int N> __device__ __forceinline__ void cpwait() {
    asm volatile("cp.async.wait_group %0;\n" :: "n"(N));
}
__device__ __forceinline__ void ldsm4(unsigned a, unsigned* r) {
    asm volatile("ldmatrix.sync.aligned.m8n8.x4.shared.b16 {%0,%1,%2,%3},[%4];\n"
                 : "=r"(r[0]), "=r"(r[1]), "=r"(r[2]), "=r"(r[3]) : "r"(a));
}
__device__ __forceinline__ void ldsm4t(unsigned a, unsigned* r) {
    asm volatile("ldmatrix.sync.aligned.m8n8.x4.trans.shared.b16 {%0,%1,%2,%3},[%4];\n"
                 : "=r"(r[0]), "=r"(r[1]), "=r"(r[2]), "=r"(r[3]) : "r"(a));
}
__device__ __forceinline__ void mmah(float* c, const unsigned* a, unsigned b0, unsigned b1) {
    asm volatile("mma.sync.aligned.m16n8k16.row.col.f32.f16.f16.f32 "
                 "{%0,%1,%2,%3},{%4,%5,%6,%7},{%8,%9},{%0,%1,%2,%3};\n"
                 : "+f"(c[0]), "+f"(c[1]), "+f"(c[2]), "+f"(c[3])
                 : "r"(a[0]), "r"(a[1]), "r"(a[2]), "r"(a[3]), "r"(b0), "r"(b1));
}
__device__ __forceinline__ unsigned packh2(float x, float y) {
    __half2 hh = __floats2half2_rn(x, y);
    return *(unsigned*)&hh;
}

// ---------------------------------------------------------------------------
// Convert weights to fp16 (once).
// ---------------------------------------------------------------------------
__global__ void splitw_kernel(const float* __restrict__ Wq,
                              const float* __restrict__ Wk,
                              const float* __restrict__ Wv)
{
    const float* Wsrc[3] = {Wq, Wk, Wv};
    int off = (blockIdx.x * 256 + threadIdx.x) * 4;
    #pragma unroll
    for (int mat = 0; mat < 3; ++mat) {
        float4 v = *(const float4*)&Wsrc[mat][off];
        uint2 p = make_uint2(packh2(v.x, v.y), packh2(v.z, v.w));
        *(uint2*)&gW3[mat*NEMB*HS + off] = p;
    }
}

// ---------------------------------------------------------------------------
// Projection: 128 rows of X per CTA -> Q,K,V. Single-term fp16: X·W.
// 512 threads = 16 warps: 8 m-groups x 2 n-groups. KT=32, double-buffered.
// ---------------------------------------------------------------------------
#define PJ_BLK 24064
#define PJ_X(s)      ((s)*PJ_BLK)
#define PJ_W(s,mat)  ((s)*PJ_BLK + 10240 + (mat)*4608)
static const int PROJ_SMEM = 2*PJ_BLK;   // 48128

__global__ __launch_bounds__(512) void proj_kernel(const float* __restrict__ x)
{
    extern __shared__ char smc[];
    const unsigned sb = su32(smc);
    const int tid = threadIdx.x, lane = tid & 31, wid = tid >> 5;
    const int wm = wid & 7, wn = wid >> 3;
    const int bt0 = blockIdx.x * 128;

    const int xrow0 = tid >> 3, xc0 = (tid & 7) * 4;
    const int xrow1 = (tid + 512) >> 3, xc1 = ((tid + 512) & 7) * 4;

    float acc[3][4][4];
    #pragma unroll
    for (int m = 0; m < 3; ++m)
        #pragma unroll
        for (int t = 0; t < 4; ++t)
            #pragma unroll
            for (int r = 0; r < 4; ++r) acc[m][t][r] = 0.f;

    // issue W(0): 768 16B-chunks (3 slabs x 256)
    #pragma unroll
    for (int r = 0; r < 2; ++r) {
        int u = tid + 512*r;
        if (u < 768) {
            int mat = u >> 8, rem = u & 255;
            int row = rem >> 3, c16 = rem & 7;
            const char* src = (const char*)(gW3 + (size_t)mat*NEMB*HS)
                            + ((size_t)row*HS + c16*8) * 2;
            cpa16(sb + PJ_W(0, mat) + row*144 + c16*16, src);
        }
    }
    cpcommit();
    float4 xr0, xr1;
    xr0 = *(const float4*)&x[(size_t)(bt0+xrow0)*NEMB + xc0];
    xr1 = *(const float4*)&x[(size_t)(bt0+xrow1)*NEMB + xc1];
    *(uint2*)((__half*)(smc + PJ_X(0)) + xrow0*LDX + xc0) =
        make_uint2(packh2(xr0.x, xr0.y), packh2(xr0.z, xr0.w));
    *(uint2*)((__half*)(smc + PJ_X(0)) + xrow1*LDX + xc1) =
        make_uint2(packh2(xr1.x, xr1.y), packh2(xr1.z, xr1.w));
    xr0 = *(const float4*)&x[(size_t)(bt0+xrow0)*NEMB + 32 + xc0];
    xr1 = *(const float4*)&x[(size_t)(bt0+xrow1)*NEMB + 32 + xc1];

    int buf = 0;
    for (int kt = 0; kt < 32; ++kt) {
        cpwait<0>();
        __syncthreads();
        if (kt < 31) {
            #pragma unroll
            for (int r = 0; r < 2; ++r) {
                int u = tid + 512*r;
                if (u < 768) {
                    int mat = u >> 8, rem = u & 255;
                    int row = rem >> 3, c16 = rem & 7;
                    const char* src = (const char*)(gW3 + (size_t)mat*NEMB*HS)
                                    + ((size_t)((kt+1)*32 + row)*HS + c16*8) * 2;
                    cpa16(sb + PJ_W(buf^1, mat) + row*144 + c16*16, src);
                }
            }
            cpcommit();
            *(uint2*)((__half*)(smc + PJ_X(buf^1)) + xrow0*LDX + xc0) =
                make_uint2(packh2(xr0.x, xr0.y), packh2(xr0.z, xr0.w));
            *(uint2*)((__half*)(smc + PJ_X(buf^1)) + xrow1*LDX + xc1) =
                make_uint2(packh2(xr1.x, xr1.y), packh2(xr1.z, xr1.w));
            if (kt < 30) {
                xr0 = *(const float4*)&x[(size_t)(bt0+xrow0)*NEMB + (kt+2)*32 + xc0];
                xr1 = *(const float4*)&x[(size_t)(bt0+xrow1)*NEMB + (kt+2)*32 + xc1];
            }
        }

        #pragma unroll
        for (int kk = 0; kk < 2; ++kk) {
            unsigned ah[4];
            unsigned ao = (unsigned)(((wm*16 + (lane&15))*LDX + kk*16 + (lane>>4)*8) * 2);
            ldsm4(sb + PJ_X(buf) + ao, ah);
            #pragma unroll
            for (int mat = 0; mat < 3; ++mat) {
                #pragma unroll
                for (int nb = 0; nb < 2; ++nb) {
                    unsigned bh[4];
                    unsigned bo = (unsigned)(((kk*16 + (lane&15))*LDB +
                                              wn*32 + nb*16 + (lane>>4)*8) * 2);
                    ldsm4t(sb + PJ_W(buf, mat) + bo, bh);
                    mmah(acc[mat][nb*2],   ah, bh[0], bh[1]);
                    mmah(acc[mat][nb*2+1], ah, bh[2], bh[3]);
                }
            }
        }
        buf ^= 1;
    }

    const int r0 = bt0 + wm*16 + (lane >> 2);
    #pragma unroll
    for (int nt = 0; nt < 4; ++nt) {
        int col = wn*32 + nt*8 + 2*(lane & 3);
        *(unsigned*)&gQ[(size_t)r0*HS + col]     = packh2(acc[0][nt][0], acc[0][nt][1]);
        *(unsigned*)&gQ[(size_t)(r0+8)*HS + col] = packh2(acc[0][nt][2], acc[0][nt][3]);
        *(unsigned*)&gK[(size_t)r0*HS + col] =
            packh2(acc[1][nt][0]*LOG2E, acc[1][nt][1]*LOG2E);
        *(unsigned*)&gK[(size_t)(r0+8)*HS + col] =
            packh2(acc[1][nt][2]*LOG2E, acc[1][nt][3]*LOG2E);
        *(unsigned*)&gV[(size_t)r0*HS + col]     = packh2(acc[2][nt][0], acc[2][nt][1]);
        *(unsigned*)&gV[(size_t)(r0+8)*HS + col] = packh2(acc[2][nt][2], acc[2][nt][3]);
    }
}

// ---------------------------------------------------------------------------
// Flash attention, split-K, fp16 single-term S and PV. Base-2 softmax.
// Row sums of P computed via MMA against an all-ones B fragment (exactly
// consistent with the fp16 P used in P·V).
// ---------------------------------------------------------------------------
#define AT_K(s) ((s)*18432)
#define AT_V(s) ((s)*18432 + 9216)
#define AT_Q 36864
static const int ATTN_SMEM = 46080;

__global__ __launch_bounds__(128, 4) void attn_kernel(float* __restrict__ out)
{
    const int c  = blockIdx.x;
    const int qt = NQT - 1 - blockIdx.y;
    const int b  = blockIdx.z;
    const int nch = (qt >> 3) + 1;
    if (c >= nch) return;
    const int kt0 = c * CHK;
    const int kt1 = min(qt, kt0 + CHK - 1);
    const int t0 = qt * 64;

    extern __shared__ char smc[];
    const unsigned sb = su32(smc);
    const int tid = threadIdx.x, lane = tid & 31, w = tid >> 5;
    const int lr = lane >> 2;
    const int lc2 = 2 * (lane & 3);

    unsigned d16[4];
    #pragma unroll
    for (int r = 0; r < 4; ++r) {
        int u = tid + 128*r;
        d16[r] = (unsigned)((u>>3)*144 + (u&7)*16);
    }

    {
        const char* gq = (const char*)gQ + (size_t)(b*TT + t0)*128;
        #pragma unroll
        for (int r = 0; r < 4; ++r) {
            int u = tid + 128*r;
            cpa16(sb + AT_Q + d16[r], gq + (size_t)u*16);
        }
        cpcommit();
    }
    {
        size_t gb = (size_t)(b*TT + kt0*64)*128;
        #pragma unroll
        for (int r = 0; r < 4; ++r) {
            int u = tid + 128*r;
            size_t go = gb + (size_t)u*16;
            cpa16(sb + AT_K(0) + d16[r], (const char*)gK + go);
            cpa16(sb + AT_V(0) + d16[r], (const char*)gV + go);
        }
        cpcommit();
    }

    cpwait<1>();
    __syncthreads();
    unsigned qh[4][4];
    #pragma unroll
    for (int kk = 0; kk < 4; ++kk) {
        unsigned ao = (unsigned)(((w*16 + (lane&15))*LDB + kk*16 + (lane>>4)*8) * 2);
        ldsm4(sb + AT_Q + ao, qh[kk]);
    }

    float o[8][4];
    #pragma unroll
    for (int t = 0; t < 8; ++t)
        #pragma unroll
        for (int r = 0; r < 4; ++r) o[t][r] = 0.f;
    float m0 = -1e30f, m1 = -1e30f, l0 = 0.f, l1 = 0.f;

    int buf = 0;
    for (int kt = kt0; kt <= kt1; ++kt) {
        cpwait<0>();
        __syncthreads();
        if (kt < kt1) {
            size_t gb = (size_t)(b*TT + (kt+1)*64)*128;
            #pragma unroll
            for (int r = 0; r < 4; ++r) {
                int u = tid + 128*r;
                size_t go = gb + (size_t)u*16;
                cpa16(sb + AT_K(buf^1) + d16[r], (const char*)gK + go);
                cpa16(sb + AT_V(buf^1) + d16[r], (const char*)gV + go);
            }
            cpcommit();
        }

        float st[8][4];
        #pragma unroll
        for (int t = 0; t < 8; ++t)
            #pragma unroll
            for (int r = 0; r < 4; ++r) st[t][r] = 0.f;
        #pragma unroll
        for (int kk = 0; kk < 4; ++kk) {
            #pragma unroll
            for (int kb = 0; kb < 4; ++kb) {
                unsigned kh[4];
                unsigned ko = (unsigned)(((kb*16 + (lane&15))*LDB + kk*16 + (lane>>4)*8) * 2);
                ldsm4(sb + AT_K(buf) + ko, kh);
                mmah(st[kb*2],   qh[kk], kh[0], kh[2]);
                mmah(st[kb*2+1], qh[kk], kh[1], kh[3]);
            }
        }

        if (kt == qt) {
            int r0 = w*16 + lr, r1 = r0 + 8;
            #pragma unroll
            for (int nt = 0; nt < 8; ++nt) {
                int cc = nt*8 + lc2;
                if (cc     > r0) st[nt][0] = -1e30f;
                if (cc + 1 > r0) st[nt][1] = -1e30f;
                if (cc     > r1) st[nt][2] = -1e30f;
                if (cc + 1 > r1) st[nt][3] = -1e30f;
            }
        }

        float mx0 = -1e30f, mx1 = -1e30f;
        #pragma unroll
        for (int nt = 0; nt < 8; ++nt) {
            mx0 = fmaxf(mx0, fmaxf(st[nt][0], st[nt][1]));
            mx1 = fmaxf(mx1, fmaxf(st[nt][2], st[nt][3]));
        }
        mx0 = fmaxf(mx0, __shfl_xor_sync(0xffffffffu, mx0, 1));
        mx0 = fmaxf(mx0, __shfl_xor_sync(0xffffffffu, mx0, 2));
        mx1 = fmaxf(mx1, __shfl_xor_sync(0xffffffffu, mx1, 1));
        mx1 = fmaxf(mx1, __shfl_xor_sync(0xffffffffu, mx1, 2));
        float mn0 = fmaxf(m0, mx0), mn1 = fmaxf(m1, mx1);
        float a0 = exp2f(m0 - mn0), a1 = exp2f(m1 - mn1);
        #pragma unroll
        for (int nt = 0; nt < 8; ++nt) {
            st[nt][0] = exp2f(st[nt][0] - mn0);
            st[nt][1] = exp2f(st[nt][1] - mn0);
            st[nt][2] = exp2f(st[nt][2] - mn1);
            st[nt][3] = exp2f(st[nt][3] - mn1);
        }
        m0 = mn0; m1 = mn1;
        #pragma unroll
        for (int nt = 0; nt < 8; ++nt) {
            o[nt][0] *= a0; o[nt][1] *= a0; o[nt][2] *= a1; o[nt][3] *= a1;
        }

        // P fragments: single fp16
        unsigned p[4][4];
        #pragma unroll
        for (int t = 0; t < 4; ++t) {
            p[t][0] = packh2(st[2*t][0],   st[2*t][1]);
            p[t][1] = packh2(st[2*t][2],   st[2*t][3]);
            p[t][2] = packh2(st[2*t+1][0], st[2*t+1][1]);
            p[t][3] = packh2(st[2*t+1][2], st[2*t+1][3]);
        }
        // Row sums of P via MMA against ones (fp32 accum, consistent with PV)
        float lacc[4] = {0.f, 0.f, 0.f, 0.f};
        #pragma unroll
        for (int t = 0; t < 4; ++t)
            mmah(lacc, p[t], ONE_H2, ONE_H2);
        l0 = l0 * a0 + lacc[0];
        l1 = l1 * a1 + lacc[2];

        // O += P · V
        #pragma unroll
        for (int t = 0; t < 4; ++t) {
            #pragma unroll
            for (int nb = 0; nb < 4; ++nb) {
                unsigned vh[4];
                unsigned vo = (unsigned)(((t*16 + (lane&15))*LDB + nb*16 + (lane>>4)*8) * 2);
                ldsm4t(sb + AT_V(buf) + vo, vh);
                mmah(o[nb*2],   p[t], vh[0], vh[1]);
                mmah(o[nb*2+1], p[t], vh[2], vh[3]);
            }
        }
        buf ^= 1;
    }

    const int rloc = w*16 + lr;
    if (nch == 1) {
        float i0 = 1.f / l0, i1 = 1.f / l1;
        size_t gr0 = (size_t)(b*TT + t0 + rloc);
        #pragma unroll
        for (int nt = 0; nt < 8; ++nt) {
            int col = nt*8 + lc2;
            *(float2*)&out[gr0*HS + col]     = make_float2(o[nt][0]*i0, o[nt][1]*i0);
            *(float2*)&out[(gr0+8)*HS + col] = make_float2(o[nt][2]*i1, o[nt][3]*i1);
        }
    } else {
        size_t slot = (size_t)(b*NQT + qt)*MAXC + c;
        __half* Op = gOp + slot*(64*HS);
        #pragma unroll
        for (int nt = 0; nt < 8; ++nt) {
            int col = nt*8 + lc2;
            *(unsigned*)&Op[rloc*HS + col]     = packh2(o[nt][0], o[nt][1]);
            *(unsigned*)&Op[(rloc+8)*HS + col] = packh2(o[nt][2], o[nt][3]);
        }
        if ((lane & 3) == 0) {
            gM[slot*64 + rloc] = m0;     gL[slot*64 + rloc] = l0;
            gM[slot*64 + rloc + 8] = m1; gL[slot*64 + rloc + 8] = l1;
        }
    }
}

// ---------------------------------------------------------------------------
// Merge split-K partials (fp16 partials, base-2 maxes).
// ---------------------------------------------------------------------------
__global__ __launch_bounds__(256) void merge_kernel(float* __restrict__ out)
{
    const int qt = CHK + blockIdx.x;
    const int b  = blockIdx.y;
    const int z  = blockIdx.z;
    const int nch = (qt >> 3) + 1;
    const int tid = threadIdx.x;
    const int row = tid >> 2;
    const int col = z*16 + (tid & 3) * 4;
    const size_t slot0 = (size_t)(b*NQT + qt)*MAXC;

    float ms = -1e30f;
    float mv[MAXC];
    #pragma unroll
    for (int c = 0; c < MAXC; ++c)
        if (c < nch) { mv[c] = gM[(slot0 + c)*64 + row]; ms = fmaxf(ms, mv[c]); }
    float lsum = 0.f;
    float sc[MAXC];
    #pragma unroll
    for (int c = 0; c < MAXC; ++c)
        if (c < nch) {
            sc[c] = exp2f(mv[c] - ms);
            lsum += gL[(slot0 + c)*64 + row] * sc[c];
        }
    float inv = 1.f / lsum;

    float4 acc = make_float4(0.f, 0.f, 0.f, 0.f);
    #pragma unroll
    for (int c = 0; c < MAXC; ++c)
        if (c < nch) {
            uint2 pv = *(const uint2*)&gOp[(slot0 + c)*(64*HS) + row*HS + col];
            float2 v0 = __half22float2(*(__half2*)&pv.x);
            float2 v1 = __half22float2(*(__half2*)&pv.y);
            acc.x += v0.x * sc[c]; acc.y += v0.y * sc[c];
            acc.z += v1.x * sc[c]; acc.w += v1.y * sc[c];
        }
    acc.x *= inv; acc.y *= inv; acc.z *= inv; acc.w *= inv;
    *(float4*)&out[(size_t)(b*TT + qt*64 + row)*HS + col] = acc;
}

// ---------------------------------------------------------------------------
extern "C" void kernel_launch(void* const* d_in, const int* in_sizes, int n_in,
                              void* d_out, int out_size)
{
    const float* x  = (const float*)d_in[0];
    const float* Wq = (const float*)d_in[1];
    const float* Wk = (const float*)d_in[2];
    const float* Wv = (const float*)d_in[3];
    float* out = (float*)d_out;
    (void)in_sizes; (void)n_in; (void)out_size;

    cudaFuncSetAttribute(proj_kernel, cudaFuncAttributeMaxDynamicSharedMemorySize, PROJ_SMEM);
    cudaFuncSetAttribute(attn_kernel, cudaFuncAttributeMaxDynamicSharedMemorySize, ATTN_SMEM);

    splitw_kernel<<<NEMB*HS/1024, 256>>>(Wq, Wk, Wv);
    proj_kernel<<<BT/128, 512, PROJ_SMEM>>>(x);
    attn_kernel<<<dim3(MAXC, NQT, BB), 128, ATTN_SMEM>>>(out);
    merge_kernel<<<dim3(NQT - CHK, BB, 4), 256>>>(out);
}

// round 15
// speedup vs baseline: 1.4866x; 1.0086x over previous
#include <cuda_runtime.h>
#include <cuda_fp16.h>
#include <cstdint>

#define NEMB 1024
#define HS 64
#define BB 8
#define TT 2048
#define BT (BB*TT)
#define LDB 72          // 16-bit elem row stride for 64-wide tiles (144B)
#define LDX 40          // fp16 row stride for 32-wide X tiles
#define NQT (TT/64)
#define CHK 8
#define MAXC 4
#define LOG2E 1.4426950408889634f
#define ONE_H2 0x3C003C00u   // half2(1.0, 1.0)

// fp16 storage: Q single, K single (pre-scaled by log2e), V single
__device__ __align__(16) __half gQ[BT*HS];
__device__ __align__(16) __half gK[BT*HS];
__device__ __align__(16) __half gV[BT*HS];
// fp16 weights, [mat][k][n]
__device__ __align__(16) __half gW3[3*NEMB*HS];
// split-K partials: O as fp16, m/l fp32
__device__ __align__(16) __half gOp[BB*NQT*MAXC*64*HS];
__device__ float gM[BB*NQT*MAXC*64];
__device__ float gL[BB*NQT*MAXC*64];

__device__ __forceinline__ unsigned su32(const void* p) {
    return (unsigned)__cvta_generic_to_shared(p);
}
__device__ __forceinline__ void cpa16(unsigned dst, const void* src) {
    asm volatile("cp.async.cg.shared.global [%0], [%1], 16;\n" :: "r"(dst), "l"(src));
}
__device__ __forceinline__ void cpcommit() { asm volatile("cp.async.commit_group;\n"); }
template<int N> __device__ __forceinline__ void cpwait() {
    asm volatile("cp.async.wait_group %0;\n" :: "n"(N));
}
__device__ __forceinline__ void ldsm4(unsigned a, unsigned* r) {
    asm volatile("ldmatrix.sync.aligned.m8n8.x4.shared.b16 {%0,%1,%2,%3},[%4];\n"
                 : "=r"(r[0]), "=r"(r[1]), "=r"(r[2]), "=r"(r[3]) : "r"(a));
}
__device__ __forceinline__ void ldsm4t(unsigned a, unsigned* r) {
    asm volatile("ldmatrix.sync.aligned.m8n8.x4.trans.shared.b16 {%0,%1,%2,%3},[%4];\n"
                 : "=r"(r[0]), "=r"(r[1]), "=r"(r[2]), "=r"(r[3]) : "r"(a));
}
__device__ __forceinline__ void mmah(float* c, const unsigned* a, unsigned b0, unsigned b1) {
    asm volatile("mma.sync.aligned.m16n8k16.row.col.f32.f16.f16.f32 "
                 "{%0,%1,%2,%3},{%4,%5,%6,%7},{%8,%9},{%0,%1,%2,%3};\n"
                 : "+f"(c[0]), "+f"(c[1]), "+f"(c[2]), "+f"(c[3])
                 : "r"(a[0]), "r"(a[1]), "r"(a[2]), "r"(a[3]), "r"(b0), "r"(b1));
}
__device__ __forceinline__ unsigned packh2(float x, float y) {
    __half2 hh = __floats2half2_rn(x, y);
    return *(unsigned*)&hh;
}
// packed softmax exp: half2( exp2(x - mn), exp2(y - mn) ) via one MUFU op
__device__ __forceinline__ unsigned exp2sub(float x, float y, __half2 mnh) {
    __half2 v = __floats2half2_rn(x, y);
    v = h2exp2(__hsub2(v, mnh));
    return *(unsigned*)&v;
}

// ---------------------------------------------------------------------------
// Convert weights to fp16 (once).
// ---------------------------------------------------------------------------
__global__ void splitw_kernel(const float* __restrict__ Wq,
                              const float* __restrict__ Wk,
                              const float* __restrict__ Wv)
{
    const float* Wsrc[3] = {Wq, Wk, Wv};
    int off = (blockIdx.x * 256 + threadIdx.x) * 4;
    #pragma unroll
    for (int mat = 0; mat < 3; ++mat) {
        float4 v = *(const float4*)&Wsrc[mat][off];
        uint2 p = make_uint2(packh2(v.x, v.y), packh2(v.z, v.w));
        *(uint2*)&gW3[mat*NEMB*HS + off] = p;
    }
}

// ---------------------------------------------------------------------------
// Projection: 128 rows of X per CTA -> Q,K,V. Single-term fp16: X·W.
// ---------------------------------------------------------------------------
#define PJ_BLK 24064
#define PJ_X(s)      ((s)*PJ_BLK)
#define PJ_W(s,mat)  ((s)*PJ_BLK + 10240 + (mat)*4608)
static const int PROJ_SMEM = 2*PJ_BLK;   // 48128

__global__ __launch_bounds__(512) void proj_kernel(const float* __restrict__ x)
{
    extern __shared__ char smc[];
    const unsigned sb = su32(smc);
    const int tid = threadIdx.x, lane = tid & 31, wid = tid >> 5;
    const int wm = wid & 7, wn = wid >> 3;
    const int bt0 = blockIdx.x * 128;

    const int xrow0 = tid >> 3, xc0 = (tid & 7) * 4;
    const int xrow1 = (tid + 512) >> 3, xc1 = ((tid + 512) & 7) * 4;

    float acc[3][4][4];
    #pragma unroll
    for (int m = 0; m < 3; ++m)
        #pragma unroll
        for (int t = 0; t < 4; ++t)
            #pragma unroll
            for (int r = 0; r < 4; ++r) acc[m][t][r] = 0.f;

    #pragma unroll
    for (int r = 0; r < 2; ++r) {
        int u = tid + 512*r;
        if (u < 768) {
            int mat = u >> 8, rem = u & 255;
            int row = rem >> 3, c16 = rem & 7;
            const char* src = (const char*)(gW3 + (size_t)mat*NEMB*HS)
                            + ((size_t)row*HS + c16*8) * 2;
            cpa16(sb + PJ_W(0, mat) + row*144 + c16*16, src);
        }
    }
    cpcommit();
    float4 xr0, xr1;
    xr0 = *(const float4*)&x[(size_t)(bt0+xrow0)*NEMB + xc0];
    xr1 = *(const float4*)&x[(size_t)(bt0+xrow1)*NEMB + xc1];
    *(uint2*)((__half*)(smc + PJ_X(0)) + xrow0*LDX + xc0) =
        make_uint2(packh2(xr0.x, xr0.y), packh2(xr0.z, xr0.w));
    *(uint2*)((__half*)(smc + PJ_X(0)) + xrow1*LDX + xc1) =
        make_uint2(packh2(xr1.x, xr1.y), packh2(xr1.z, xr1.w));
    xr0 = *(const float4*)&x[(size_t)(bt0+xrow0)*NEMB + 32 + xc0];
    xr1 = *(const float4*)&x[(size_t)(bt0+xrow1)*NEMB + 32 + xc1];

    int buf = 0;
    for (int kt = 0; kt < 32; ++kt) {
        cpwait<0>();
        __syncthreads();
        if (kt < 31) {
            #pragma unroll
            for (int r = 0; r < 2; ++r) {
                int u = tid + 512*r;
                if (u < 768) {
                    int mat = u >> 8, rem = u & 255;
                    int row = rem >> 3, c16 = rem & 7;
                    const char* src = (const char*)(gW3 + (size_t)mat*NEMB*HS)
                                    + ((size_t)((kt+1)*32 + row)*HS + c16*8) * 2;
                    cpa16(sb + PJ_W(buf^1, mat) + row*144 + c16*16, src);
                }
            }
            cpcommit();
            *(uint2*)((__half*)(smc + PJ_X(buf^1)) + xrow0*LDX + xc0) =
                make_uint2(packh2(xr0.x, xr0.y), packh2(xr0.z, xr0.w));
            *(uint2*)((__half*)(smc + PJ_X(buf^1)) + xrow1*LDX + xc1) =
                make_uint2(packh2(xr1.x, xr1.y), packh2(xr1.z, xr1.w));
            if (kt < 30) {
                xr0 = *(const float4*)&x[(size_t)(bt0+xrow0)*NEMB + (kt+2)*32 + xc0];
                xr1 = *(const float4*)&x[(size_t)(bt0+xrow1)*NEMB + (kt+2)*32 + xc1];
            }
        }

        #pragma unroll
        for (int kk = 0; kk < 2; ++kk) {
            unsigned ah[4];
            unsigned ao = (unsigned)(((wm*16 + (lane&15))*LDX + kk*16 + (lane>>4)*8) * 2);
            ldsm4(sb + PJ_X(buf) + ao, ah);
            #pragma unroll
            for (int mat = 0; mat < 3; ++mat) {
                #pragma unroll
                for (int nb = 0; nb < 2; ++nb) {
                    unsigned bh[4];
                    unsigned bo = (unsigned)(((kk*16 + (lane&15))*LDB +
                                              wn*32 + nb*16 + (lane>>4)*8) * 2);
                    ldsm4t(sb + PJ_W(buf, mat) + bo, bh);
                    mmah(acc[mat][nb*2],   ah, bh[0], bh[1]);
                    mmah(acc[mat][nb*2+1], ah, bh[2], bh[3]);
                }
            }
        }
        buf ^= 1;
    }

    const int r0 = bt0 + wm*16 + (lane >> 2);
    #pragma unroll
    for (int nt = 0; nt < 4; ++nt) {
        int col = wn*32 + nt*8 + 2*(lane & 3);
        *(unsigned*)&gQ[(size_t)r0*HS + col]     = packh2(acc[0][nt][0], acc[0][nt][1]);
        *(unsigned*)&gQ[(size_t)(r0+8)*HS + col] = packh2(acc[0][nt][2], acc[0][nt][3]);
        *(unsigned*)&gK[(size_t)r0*HS + col] =
            packh2(acc[1][nt][0]*LOG2E, acc[1][nt][1]*LOG2E);
        *(unsigned*)&gK[(size_t)(r0+8)*HS + col] =
            packh2(acc[1][nt][2]*LOG2E, acc[1][nt][3]*LOG2E);
        *(unsigned*)&gV[(size_t)r0*HS + col]     = packh2(acc[2][nt][0], acc[2][nt][1]);
        *(unsigned*)&gV[(size_t)(r0+8)*HS + col] = packh2(acc[2][nt][2], acc[2][nt][3]);
    }
}

// ---------------------------------------------------------------------------
// Flash attention, split-K, fp16 single-term S and PV. Base-2 softmax with
// packed fp16 exponentials (h2exp2: one MUFU per 2 elements); P row sums via
// MMA against ones.
// ---------------------------------------------------------------------------
#define AT_K(s) ((s)*18432)
#define AT_V(s) ((s)*18432 + 9216)
#define AT_Q 36864
static const int ATTN_SMEM = 46080;

__global__ __launch_bounds__(128, 4) void attn_kernel(float* __restrict__ out)
{
    const int c  = blockIdx.x;
    const int qt = NQT - 1 - blockIdx.y;
    const int b  = blockIdx.z;
    const int nch = (qt >> 3) + 1;
    if (c >= nch) return;
    const int kt0 = c * CHK;
    const int kt1 = min(qt, kt0 + CHK - 1);
    const int t0 = qt * 64;

    extern __shared__ char smc[];
    const unsigned sb = su32(smc);
    const int tid = threadIdx.x, lane = tid & 31, w = tid >> 5;
    const int lr = lane >> 2;
    const int lc2 = 2 * (lane & 3);

    unsigned d16[4];
    #pragma unroll
    for (int r = 0; r < 4; ++r) {
        int u = tid + 128*r;
        d16[r] = (unsigned)((u>>3)*144 + (u&7)*16);
    }

    {
        const char* gq = (const char*)gQ + (size_t)(b*TT + t0)*128;
        #pragma unroll
        for (int r = 0; r < 4; ++r) {
            int u = tid + 128*r;
            cpa16(sb + AT_Q + d16[r], gq + (size_t)u*16);
        }
        cpcommit();
    }
    {
        size_t gb = (size_t)(b*TT + kt0*64)*128;
        #pragma unroll
        for (int r = 0; r < 4; ++r) {
            int u = tid + 128*r;
            size_t go = gb + (size_t)u*16;
            cpa16(sb + AT_K(0) + d16[r], (const char*)gK + go);
            cpa16(sb + AT_V(0) + d16[r], (const char*)gV + go);
        }
        cpcommit();
    }

    cpwait<1>();
    __syncthreads();
    unsigned qh[4][4];
    #pragma unroll
    for (int kk = 0; kk < 4; ++kk) {
        unsigned ao = (unsigned)(((w*16 + (lane&15))*LDB + kk*16 + (lane>>4)*8) * 2);
        ldsm4(sb + AT_Q + ao, qh[kk]);
    }

    float o[8][4];
    #pragma unroll
    for (int t = 0; t < 8; ++t)
        #pragma unroll
        for (int r = 0; r < 4; ++r) o[t][r] = 0.f;
    float m0 = -1e30f, m1 = -1e30f, l0 = 0.f, l1 = 0.f;

    int buf = 0;
    for (int kt = kt0; kt <= kt1; ++kt) {
        cpwait<0>();
        __syncthreads();
        if (kt < kt1) {
            size_t gb = (size_t)(b*TT + (kt+1)*64)*128;
            #pragma unroll
            for (int r = 0; r < 4; ++r) {
                int u = tid + 128*r;
                size_t go = gb + (size_t)u*16;
                cpa16(sb + AT_K(buf^1) + d16[r], (const char*)gK + go);
                cpa16(sb + AT_V(buf^1) + d16[r], (const char*)gV + go);
            }
            cpcommit();
        }

        float st[8][4];
        #pragma unroll
        for (int t = 0; t < 8; ++t)
            #pragma unroll
            for (int r = 0; r < 4; ++r) st[t][r] = 0.f;
        #pragma unroll
        for (int kk = 0; kk < 4; ++kk) {
            #pragma unroll
            for (int kb = 0; kb < 4; ++kb) {
                unsigned kh[4];
                unsigned ko = (unsigned)(((kb*16 + (lane&15))*LDB + kk*16 + (lane>>4)*8) * 2);
                ldsm4(sb + AT_K(buf) + ko, kh);
                mmah(st[kb*2],   qh[kk], kh[0], kh[2]);
                mmah(st[kb*2+1], qh[kk], kh[1], kh[3]);
            }
        }

        if (kt == qt) {
            int r0 = w*16 + lr, r1 = r0 + 8;
            #pragma unroll
            for (int nt = 0; nt < 8; ++nt) {
                int cc = nt*8 + lc2;
                if (cc     > r0) st[nt][0] = -1e30f;
                if (cc + 1 > r0) st[nt][1] = -1e30f;
                if (cc     > r1) st[nt][2] = -1e30f;
                if (cc + 1 > r1) st[nt][3] = -1e30f;
            }
        }

        float mx0 = -1e30f, mx1 = -1e30f;
        #pragma unroll
        for (int nt = 0; nt < 8; ++nt) {
            mx0 = fmaxf(mx0, fmaxf(st[nt][0], st[nt][1]));
            mx1 = fmaxf(mx1, fmaxf(st[nt][2], st[nt][3]));
        }
        mx0 = fmaxf(mx0, __shfl_xor_sync(0xffffffffu, mx0, 1));
        mx0 = fmaxf(mx0, __shfl_xor_sync(0xffffffffu, mx0, 2));
        mx1 = fmaxf(mx1, __shfl_xor_sync(0xffffffffu, mx1, 1));
        mx1 = fmaxf(mx1, __shfl_xor_sync(0xffffffffu, mx1, 2));
        float mn0 = fmaxf(m0, mx0), mn1 = fmaxf(m1, mx1);
        float a0 = exp2f(m0 - mn0), a1 = exp2f(m1 - mn1);
        m0 = mn0; m1 = mn1;
        #pragma unroll
        for (int nt = 0; nt < 8; ++nt) {
            o[nt][0] *= a0; o[nt][1] *= a0; o[nt][2] *= a1; o[nt][3] *= a1;
        }

        // P fragments directly via packed fp16 exp (h2exp2): one MUFU / 2 elems
        const __half2 mnh0 = __float2half2_rn(mn0);
        const __half2 mnh1 = __float2half2_rn(mn1);
        unsigned p[4][4];
        #pragma unroll
        for (int t = 0; t < 4; ++t) {
            p[t][0] = exp2sub(st[2*t][0],   st[2*t][1],   mnh0);
            p[t][1] = exp2sub(st[2*t][2],   st[2*t][3],   mnh1);
            p[t][2] = exp2sub(st[2*t+1][0], st[2*t+1][1], mnh0);
            p[t][3] = exp2sub(st[2*t+1][2], st[2*t+1][3], mnh1);
        }
        // Row sums of P via MMA against ones (fp32 accum, consistent with PV)
        float lacc[4] = {0.f, 0.f, 0.f, 0.f};
        #pragma unroll
        for (int t = 0; t < 4; ++t)
            mmah(lacc, p[t], ONE_H2, ONE_H2);
        l0 = l0 * a0 + lacc[0];
        l1 = l1 * a1 + lacc[2];

        // O += P · V
        #pragma unroll
        for (int t = 0; t < 4; ++t) {
            #pragma unroll
            for (int nb = 0; nb < 4; ++nb) {
                unsigned vh[4];
                unsigned vo = (unsigned)(((t*16 + (lane&15))*LDB + nb*16 + (lane>>4)*8) * 2);
                ldsm4t(sb + AT_V(buf) + vo, vh);
                mmah(o[nb*2],   p[t], vh[0], vh[1]);
                mmah(o[nb*2+1], p[t], vh[2], vh[3]);
            }
        }
        buf ^= 1;
    }

    const int rloc = w*16 + lr;
    if (nch == 1) {
        float i0 = 1.f / l0, i1 = 1.f / l1;
        size_t gr0 = (size_t)(b*TT + t0 + rloc);
        #pragma unroll
        for (int nt = 0; nt < 8; ++nt) {
            int col = nt*8 + lc2;
            *(float2*)&out[gr0*HS + col]     = make_float2(o[nt][0]*i0, o[nt][1]*i0);
            *(float2*)&out[(gr0+8)*HS + col] = make_float2(o[nt][2]*i1, o[nt][3]*i1);
        }
    } else {
        size_t slot = (size_t)(b*NQT + qt)*MAXC + c;
        __half* Op = gOp + slot*(64*HS);
        #pragma unroll
        for (int nt = 0; nt < 8; ++nt) {
            int col = nt*8 + lc2;
            *(unsigned*)&Op[rloc*HS + col]     = packh2(o[nt][0], o[nt][1]);
            *(unsigned*)&Op[(rloc+8)*HS + col] = packh2(o[nt][2], o[nt][3]);
        }
        if ((lane & 3) == 0) {
            gM[slot*64 + rloc] = m0;     gL[slot*64 + rloc] = l0;
            gM[slot*64 + rloc + 8] = m1; gL[slot*64 + rloc + 8] = l1;
        }
    }
}

// ---------------------------------------------------------------------------
// Merge split-K partials (fp16 partials, base-2 maxes).
// ---------------------------------------------------------------------------
__global__ __launch_bounds__(256) void merge_kernel(float* __restrict__ out)
{
    const int qt = CHK + blockIdx.x;
    const int b  = blockIdx.y;
    const int z  = blockIdx.z;
    const int nch = (qt >> 3) + 1;
    const int tid = threadIdx.x;
    const int row = tid >> 2;
    const int col = z*16 + (tid & 3) * 4;
    const size_t slot0 = (size_t)(b*NQT + qt)*MAXC;

    float ms = -1e30f;
    float mv[MAXC];
    #pragma unroll
    for (int c = 0; c < MAXC; ++c)
        if (c < nch) { mv[c] = gM[(slot0 + c)*64 + row]; ms = fmaxf(ms, mv[c]); }
    float lsum = 0.f;
    float sc[MAXC];
    #pragma unroll
    for (int c = 0; c < MAXC; ++c)
        if (c < nch) {
            sc[c] = exp2f(mv[c] - ms);
            lsum += gL[(slot0 + c)*64 + row] * sc[c];
        }
    float inv = 1.f / lsum;

    float4 acc = make_float4(0.f, 0.f, 0.f, 0.f);
    #pragma unroll
    for (int c = 0; c < MAXC; ++c)
        if (c < nch) {
            uint2 pv = *(const uint2*)&gOp[(slot0 + c)*(64*HS) + row*HS + col];
            float2 v0 = __half22float2(*(__half2*)&pv.x);
            float2 v1 = __half22float2(*(__half2*)&pv.y);
            acc.x += v0.x * sc[c]; acc.y += v0.y * sc[c];
            acc.z += v1.x * sc[c]; acc.w += v1.y * sc[c];
        }
    acc.x *= inv; acc.y *= inv; acc.z *= inv; acc.w *= inv;
    *(float4*)&out[(size_t)(b*TT + qt*64 + row)*HS + col] = acc;
}

// ---------------------------------------------------------------------------
extern "C" void kernel_launch(void* const* d_in, const int* in_sizes, int n_in,
                              void* d_out, int out_size)
{
    const float* x  = (const float*)d_in[0];
    const float* Wq = (const float*)d_in[1];
    const float* Wk = (const float*)d_in[2];
    const float* Wv = (const float*)d_in[3];
    float* out = (float*)d_out;
    (void)in_sizes; (void)n_in; (void)out_size;

    cudaFuncSetAttribute(proj_kernel, cudaFuncAttributeMaxDynamicSharedMemorySize, PROJ_SMEM);
    cudaFuncSetAttribute(attn_kernel, cudaFuncAttributeMaxDynamicSharedMemorySize, ATTN_SMEM);

    splitw_kernel<<<NEMB*HS/1024, 256>>>(Wq, Wk, Wv);
    proj_kernel<<<BT/128, 512, PROJ_SMEM>>>(x);
    attn_kernel<<<dim3(MAXC, NQT, BB), 128, ATTN_SMEM>>>(out);
    merge_kernel<<<dim3(NQT - CHK, BB, 4), 256>>>(out);
}